// round 4
// baseline (speedup 1.0000x reference)
#include <cuda_runtime.h>
#include <stdint.h>

#define NUM_CLASSES 20
#define B    8
#define NV   5
#define CH   3
#define HH   120
#define WW   160
#define HW   (HH*WW)        // 19200
#define NPIX (NV*HW)        // 96000
#define PP   131072
#define KNN  3

// Scratch: channel-last packed image, one float4 per (b, v*h*w + pix).
// 8 * 96000 * 16B = 12.3 MB (fits in L2 -> gathers hit cache).
__device__ float4 g_packed[B * NPIX];

// ---------------------------------------------------------------------------
// Kernel 1: pack images [b, nv, c, h, w] -> float4[b*NPIX] (channel-last)
// ---------------------------------------------------------------------------
__global__ void pack_kernel(const float* __restrict__ images) {
    int i = blockIdx.x * blockDim.x + threadIdx.x;
    if (i >= B * NPIX) return;
    int b   = i / NPIX;
    int r   = i - b * NPIX;
    int v   = r / HW;
    int pix = r - v * HW;
    // images offset: ((b*NV + v)*CH + c)*HW + pix
    const float* base = images + ((size_t)(b * NV + v) * CH) * HW + pix;
    g_packed[i] = make_float4(base[0], base[HW], base[2 * HW], 0.0f);
}

// ---------------------------------------------------------------------------
// Kernel 2: per point: gather 3 neighbors (float4 each), mean, 20x3 matvec,
// write 20 outputs. Each thread handles 4 consecutive points so every output
// store is a coalesced STG.128 along the P axis.
// knn indices are INT32 (JAX downcasts int64 without x64 mode; R1 OOB fault
// at 2x read size fingerprints this). Indices clamped defensively so a wrong
// dtype guess surfaces as rel_err, never as an illegal access.
// ---------------------------------------------------------------------------
__global__ void gather_matvec_kernel(const int* __restrict__ knn,
                                     const float* __restrict__ W2d,
                                     const float* __restrict__ b2d,
                                     float* __restrict__ out) {
    __shared__ float sW[NUM_CLASSES * 3];
    __shared__ float sB[NUM_CLASSES];
    {
        int t = threadIdx.x;
        if (t < NUM_CLASSES * 3) sW[t] = W2d[t];
        if (t < NUM_CLASSES)     sB[t] = b2d[t];
    }
    __syncthreads();

    const int PTS_PER_THREAD = 4;
    int gid = blockIdx.x * blockDim.x + threadIdx.x;   // 0 .. B*PP/4-1
    int b   = gid / (PP / PTS_PER_THREAD);
    int p0  = (gid - b * (PP / PTS_PER_THREAD)) * PTS_PER_THREAD;

    // 12 contiguous int32 indices per thread (3 per point x 4 points).
    // Byte offset = (b*PP + p0)*12, p0 % 4 == 0 -> multiple of 48 -> 16B aligned.
    const int4* ip = reinterpret_cast<const int4*>(
        knn + ((size_t)b * PP + p0) * KNN);
    int idx[12];
    #pragma unroll
    for (int j = 0; j < 3; j++) {
        int4 v = ip[j];
        idx[4 * j + 0] = v.x;
        idx[4 * j + 1] = v.y;
        idx[4 * j + 2] = v.z;
        idx[4 * j + 3] = v.w;
    }
    #pragma unroll
    for (int j = 0; j < 12; j++) {
        int v = idx[j];
        v = v < 0 ? 0 : v;
        v = v >= NPIX ? NPIX - 1 : v;
        idx[j] = v;
    }

    const float4* pk = g_packed + b * NPIX;

    // Issue all 12 gathers independently (MLP ~ 12) before reducing.
    float4 g[12];
    #pragma unroll
    for (int j = 0; j < 12; j++) g[j] = pk[idx[j]];

    float mx[4], my[4], mz[4];
    #pragma unroll
    for (int j = 0; j < 4; j++) {
        const float inv3 = 1.0f / 3.0f;
        mx[j] = (g[3*j].x + g[3*j+1].x + g[3*j+2].x) * inv3;
        my[j] = (g[3*j].y + g[3*j+1].y + g[3*j+2].y) * inv3;
        mz[j] = (g[3*j].z + g[3*j+1].z + g[3*j+2].z) * inv3;
    }

    float* ob = out + (size_t)b * NUM_CLASSES * PP + p0;
    #pragma unroll
    for (int o = 0; o < NUM_CLASSES; o++) {
        float w0 = sW[o * 3 + 0];
        float w1 = sW[o * 3 + 1];
        float w2 = sW[o * 3 + 2];
        float bb = sB[o];
        float4 r;
        r.x = bb + w0 * mx[0] + w1 * my[0] + w2 * mz[0];
        r.y = bb + w0 * mx[1] + w1 * my[1] + w2 * mz[1];
        r.z = bb + w0 * mx[2] + w1 * my[2] + w2 * mz[2];
        r.w = bb + w0 * mx[3] + w1 * my[3] + w2 * mz[3];
        *reinterpret_cast<float4*>(ob + (size_t)o * PP) = r;
    }
}

// ---------------------------------------------------------------------------
extern "C" void kernel_launch(void* const* d_in, const int* in_sizes, int n_in,
                              void* d_out, int out_size) {
    const float* images = (const float*)d_in[0];  // [8,5,3,120,160] f32
    const int*   knn    = (const int*)d_in[1];    // [8,131072,3] int32
    const float* W2d    = (const float*)d_in[2];  // [20,3]
    const float* b2d    = (const float*)d_in[3];  // [20]
    float*       out    = (float*)d_out;          // [8,20,131072] f32

    (void)in_sizes; (void)n_in; (void)out_size;

    {
        int n = B * NPIX;                 // 768000
        int threads = 512;
        int blocks = (n + threads - 1) / threads;
        pack_kernel<<<blocks, threads>>>(images);
    }
    {
        int n = B * PP / 4;               // 262144 threads
        int threads = 256;
        int blocks = n / threads;         // 1024
        gather_matvec_kernel<<<blocks, threads>>>(knn, W2d, b2d, out);
    }
}

// round 5
// speedup vs baseline: 1.0626x; 1.0626x over previous
#include <cuda_runtime.h>
#include <stdint.h>

#define NUM_CLASSES 20
#define B    8
#define NV   5
#define CH   3
#define HH   120
#define WW   160
#define HW   (HH*WW)        // 19200
#define NPIX (NV*HW)        // 96000
#define PP   131072
#define KNN  3

// Channel-last packed image: one float4 per (b, v*h*w + pix). 12.3 MB.
__device__ float4 g_packed[B * NPIX];

// ---------------------------------------------------------------------------
// Kernel 1: pack images [b, nv, c, h, w] -> float4[b*NPIX] (channel-last).
// Vectorized: each thread transposes 4 consecutive pixels (3x LDG.128 in,
// 4x STG.128 out).
// ---------------------------------------------------------------------------
__global__ void pack_kernel(const float* __restrict__ images) {
    int i = blockIdx.x * blockDim.x + threadIdx.x;   // 0 .. B*NPIX/4-1
    if (i >= B * NPIX / 4) return;
    int pix4 = i * 4;
    int b    = pix4 / NPIX;
    int r    = pix4 - b * NPIX;
    int v    = r / HW;
    int pix  = r - v * HW;                            // multiple of 4

    const float* base = images + ((size_t)(b * NV + v) * CH) * HW + pix;
    float4 c0 = *reinterpret_cast<const float4*>(base);
    float4 c1 = *reinterpret_cast<const float4*>(base + HW);
    float4 c2 = *reinterpret_cast<const float4*>(base + 2 * HW);

    float4* dst = g_packed + pix4;
    dst[0] = make_float4(c0.x, c1.x, c2.x, 0.0f);
    dst[1] = make_float4(c0.y, c1.y, c2.y, 0.0f);
    dst[2] = make_float4(c0.z, c1.z, c2.z, 0.0f);
    dst[3] = make_float4(c0.w, c1.w, c2.w, 0.0f);
}

// ---------------------------------------------------------------------------
// Kernel 2: 2 points per thread. Gather 6 neighbors (float4), mean per point,
// 20x3 matvec, 20 float2 streaming stores (st.global.cs keeps the packed
// table resident in L2 instead of being evicted by the 84MB output stream).
// knn indices are INT32.
// ---------------------------------------------------------------------------
__global__ void gather_matvec_kernel(const int* __restrict__ knn,
                                     const float* __restrict__ W2d,
                                     const float* __restrict__ b2d,
                                     float* __restrict__ out) {
    __shared__ float sW[NUM_CLASSES * 3];
    __shared__ float sB[NUM_CLASSES];
    {
        int t = threadIdx.x;
        if (t < NUM_CLASSES * 3) sW[t] = W2d[t];
        if (t < NUM_CLASSES)     sB[t] = b2d[t];
    }
    __syncthreads();

    const int PPT = 2;                                   // points per thread
    int gid = blockIdx.x * blockDim.x + threadIdx.x;     // 0 .. B*PP/2-1
    int b   = gid / (PP / PPT);
    int p0  = (gid - b * (PP / PPT)) * PPT;

    // 6 contiguous int32 indices; byte offset = (b*PP+p0)*12 = mult of 24 ->
    // 8B-aligned, read as 3x int2.
    const int2* ip = reinterpret_cast<const int2*>(
        knn + ((size_t)b * PP + p0) * KNN);
    int2 i0 = ip[0], i1 = ip[1], i2 = ip[2];
    int idx[6] = { i0.x, i0.y, i1.x, i1.y, i2.x, i2.y };
    #pragma unroll
    for (int j = 0; j < 6; j++) {
        int v = idx[j];
        v = v < 0 ? 0 : v;
        v = v >= NPIX ? NPIX - 1 : v;
        idx[j] = v;
    }

    const float4* pk = g_packed + b * NPIX;
    float4 g[6];
    #pragma unroll
    for (int j = 0; j < 6; j++) g[j] = __ldg(&pk[idx[j]]);

    const float inv3 = 1.0f / 3.0f;
    float mx0 = (g[0].x + g[1].x + g[2].x) * inv3;
    float my0 = (g[0].y + g[1].y + g[2].y) * inv3;
    float mz0 = (g[0].z + g[1].z + g[2].z) * inv3;
    float mx1 = (g[3].x + g[4].x + g[5].x) * inv3;
    float my1 = (g[3].y + g[4].y + g[5].y) * inv3;
    float mz1 = (g[3].z + g[4].z + g[5].z) * inv3;

    float* ob = out + (size_t)b * NUM_CLASSES * PP + p0;
    #pragma unroll
    for (int o = 0; o < NUM_CLASSES; o++) {
        float w0 = sW[o * 3 + 0];
        float w1 = sW[o * 3 + 1];
        float w2 = sW[o * 3 + 2];
        float bb = sB[o];
        float2 r;
        r.x = bb + w0 * mx0 + w1 * my0 + w2 * mz0;
        r.y = bb + w0 * mx1 + w1 * my1 + w2 * mz1;
        // streaming store: don't pollute L2 (protect the gather table)
        __stcs(reinterpret_cast<float2*>(ob + (size_t)o * PP), r);
    }
}

// ---------------------------------------------------------------------------
extern "C" void kernel_launch(void* const* d_in, const int* in_sizes, int n_in,
                              void* d_out, int out_size) {
    const float* images = (const float*)d_in[0];  // [8,5,3,120,160] f32
    const int*   knn    = (const int*)d_in[1];    // [8,131072,3] int32
    const float* W2d    = (const float*)d_in[2];  // [20,3]
    const float* b2d    = (const float*)d_in[3];  // [20]
    float*       out    = (float*)d_out;          // [8,20,131072] f32

    (void)in_sizes; (void)n_in; (void)out_size;

    {
        int n = B * NPIX / 4;             // 192000
        int threads = 256;
        int blocks = (n + threads - 1) / threads;
        pack_kernel<<<blocks, threads>>>(images);
    }
    {
        int n = B * PP / 2;               // 524288 threads
        int threads = 256;
        int blocks = n / threads;         // 2048
        gather_matvec_kernel<<<blocks, threads>>>(knn, W2d, b2d, out);
    }
}